// round 5
// baseline (speedup 1.0000x reference)
#include <cuda_runtime.h>
#include <cuda_bf16.h>
#include <cstdint>

#define N_NODES 50000
#define N_EDGES 500000
#define DIM     128
#define OUT_DIM 64
#define N_GRAPHS 512

// ---------------- device scratch (static, allowed) ----------------
__device__ float d_bufA[N_NODES * DIM];   // activations (agg output)
__device__ float d_bufB[N_NODES * DIM];   // h = act @ W (gemm output)
__device__ float d_deg[N_NODES];
__device__ float d_dinv[N_NODES];
__device__ float d_dinv2[N_NODES];
__device__ int   d_count[N_NODES];
__device__ int   d_off[N_NODES + 1];
__device__ int   d_wp[N_NODES];
__device__ int   d_bsum[64];
__device__ int   d_src[N_EDGES];
__device__ float d_coef[N_EDGES];
__device__ float d_sums[N_GRAPHS * DIM];
__device__ float d_gcnt[N_GRAPHS];
__device__ int   d_idx64;                 // 1 if indices are int64, 0 if int32

// ---------------- index dtype probe + dual-path accessor ----------------
__global__ void probe_kernel(const void* __restrict__ ei) {
    // One thread. int64 data: first 16 values all in [0, N_NODES).
    // int32 data read as int64: value < 2^32 only if the odd word is 0 (p~2e-5).
    const long long* p = (const long long*)ei;
    int ok = 0;
    for (int i = 0; i < 16; i++) {
        long long v = p[i];
        if (v >= 0 && v < N_NODES) ok++;
    }
    d_idx64 = (ok >= 15) ? 1 : 0;
}

__device__ __forceinline__ int load_idx(const void* __restrict__ p, int i, int is64) {
    if (is64) return (int)((const long long*)p)[i];
    return ((const int*)p)[i];
}

// ---------------- f32x2 packed helpers (Blackwell) ----------------
__device__ __forceinline__ unsigned long long pack2(float a, float b) {
    unsigned long long r;
    asm("mov.b64 %0, {%1, %2};" : "=l"(r) : "f"(a), "f"(b));
    return r;
}
__device__ __forceinline__ float2 unpack2(unsigned long long v) {
    float2 r;
    asm("mov.b64 {%0, %1}, %2;" : "=f"(r.x), "=f"(r.y) : "l"(v));
    return r;
}
__device__ __forceinline__ void fma2(unsigned long long& d, unsigned long long a,
                                     unsigned long long b) {
    asm("fma.rn.f32x2 %0, %1, %2, %0;" : "+l"(d) : "l"(a), "l"(b));
}

// ---------------- init: deg=1 (self loop), counters=0 ----------------
__global__ void init_kernel() {
    int i = blockIdx.x * blockDim.x + threadIdx.x;
    if (i < N_NODES) { d_deg[i] = 1.0f; d_count[i] = 0; }
    if (i < N_GRAPHS * DIM) d_sums[i] = 0.0f;
    if (i < N_GRAPHS) d_gcnt[i] = 0.0f;
}

// ---------------- degree + in-edge histogram ----------------
__global__ void deg_kernel(const void* __restrict__ ei,
                           const float* __restrict__ ew) {
    int e = blockIdx.x * blockDim.x + threadIdx.x;
    if (e >= N_EDGES) return;
    int is64 = d_idx64;
    int c = load_idx(ei, N_EDGES + e, is64);
    atomicAdd(&d_deg[c], ew[e]);
    atomicAdd(&d_count[c], 1);
}

// ---------------- dinv + per-graph node counts ----------------
__global__ void dinv_kernel(const void* __restrict__ batch) {
    int i = blockIdx.x * blockDim.x + threadIdx.x;
    if (i >= N_NODES) return;
    int is64 = d_idx64;
    float d  = d_deg[i];
    float di = rsqrtf(d);     // deg >= 1 always (self loop)
    d_dinv[i]  = di;
    d_dinv2[i] = di * di;
    atomicAdd(&d_gcnt[load_idx(batch, i, is64)], 1.0f);
}

// ---------------- 3-phase exclusive scan of d_count -> d_off ----------------
__global__ void scan1_kernel() {   // 49 blocks x 1024
    __shared__ int wsum[32];
    int tid = threadIdx.x;
    int i = blockIdx.x * 1024 + tid;
    int v = (i < N_NODES) ? d_count[i] : 0;
    int lane = tid & 31, wid = tid >> 5;
    int s = v;
    #pragma unroll
    for (int o = 1; o < 32; o <<= 1) {
        int t = __shfl_up_sync(0xFFFFFFFFu, s, o);
        if (lane >= o) s += t;
    }
    if (lane == 31) wsum[wid] = s;
    __syncthreads();
    if (wid == 0) {
        int ws = wsum[lane];
        int orig = ws;
        #pragma unroll
        for (int o = 1; o < 32; o <<= 1) {
            int t = __shfl_up_sync(0xFFFFFFFFu, ws, o);
            if (lane >= o) ws += t;
        }
        wsum[lane] = ws - orig;   // exclusive warp offsets
    }
    __syncthreads();
    int excl = s - v + wsum[wid];
    if (i < N_NODES) d_off[i] = excl;
    if (tid == 1023) d_bsum[blockIdx.x] = s + wsum[wid]; // block total
}

__global__ void scan2_kernel() {   // 1 block x 64
    __shared__ int sh[64];
    int tid = threadIdx.x;
    int v = (tid < 49) ? d_bsum[tid] : 0;
    sh[tid] = v;
    __syncthreads();
    for (int o = 1; o < 64; o <<= 1) {
        int t = (tid >= o) ? sh[tid - o] : 0;
        __syncthreads();
        sh[tid] += t;
        __syncthreads();
    }
    if (tid < 49) d_bsum[tid] = sh[tid] - v;  // exclusive
}

__global__ void scan3_kernel() {
    int i = blockIdx.x * blockDim.x + threadIdx.x;
    if (i < N_NODES) {
        int o = d_off[i] + d_bsum[i >> 10];
        d_off[i] = o;
        d_wp[i]  = o;
    }
    if (i == 0) d_off[N_NODES] = N_EDGES;
}

// ---------------- CSR fill: (src, coef) per destination ----------------
__global__ void csr_fill_kernel(const void* __restrict__ ei,
                                const float* __restrict__ ew) {
    int e = blockIdx.x * blockDim.x + threadIdx.x;
    if (e >= N_EDGES) return;
    int is64 = d_idx64;
    int r = load_idx(ei, e, is64);
    int c = load_idx(ei, N_EDGES + e, is64);
    int p = atomicAdd(&d_wp[c], 1);
    d_src[p]  = r;
    d_coef[p] = ew[e] * d_dinv[r] * d_dinv[c];
}

// ---------------- GEMM: d_bufB[N,128] = A[N,128] @ W[128,128] ----------------
// A = (use_ext ? Xext : d_bufA). Static 48KB smem, K chunked into 2x64.
__global__ void __launch_bounds__(256, 2) gemm_kernel(const float* __restrict__ Xext,
                                                      const float* __restrict__ W,
                                                      int use_ext) {
    __shared__ float As[64 * 64];    // 16KB: 64 rows x 64 k
    __shared__ float Ws[64 * 128];   // 32KB: 64 k   x 128 cols
    const float* A = use_ext ? Xext : (const float*)d_bufA;

    int tid = threadIdx.x;
    int m0 = blockIdx.x * 64;
    int tx = tid & 31, ty = tid >> 5;   // tx: 4-col group, ty: 8-row group

    unsigned long long acc[16];
    #pragma unroll
    for (int i = 0; i < 16; i++) acc[i] = 0ull;

    #pragma unroll
    for (int kc = 0; kc < 2; kc++) {
        // load W chunk: rows kc*64..kc*64+63, all 128 cols (2048 float4)
        #pragma unroll
        for (int it = 0; it < 8; it++) {
            int idx = tid + it * 256;
            ((float4*)Ws)[idx] = ((const float4*)(W + kc * 64 * DIM))[idx];
        }
        // load A chunk: 64 rows x 64 k (1024 float4)
        #pragma unroll
        for (int it = 0; it < 4; it++) {
            int idx = tid + it * 256;            // 0..1023
            int r = idx >> 4, c4 = idx & 15;
            int gr = m0 + r;
            float4 v = make_float4(0.f, 0.f, 0.f, 0.f);
            if (gr < N_NODES)
                v = *(const float4*)&A[(size_t)gr * DIM + kc * 64 + c4 * 4];
            ((float4*)As)[r * 16 + c4] = v;
        }
        __syncthreads();

        #pragma unroll 4
        for (int k0 = 0; k0 < 64; k0 += 4) {
            float4 a4[8];
            #pragma unroll
            for (int i = 0; i < 8; i++)
                a4[i] = *(float4*)&As[(ty * 8 + i) * 64 + k0];   // broadcast
            #pragma unroll
            for (int kk = 0; kk < 4; kk++) {
                float4 b = *(float4*)&Ws[(k0 + kk) * DIM + tx * 4];
                unsigned long long b01 = pack2(b.x, b.y);
                unsigned long long b23 = pack2(b.z, b.w);
                #pragma unroll
                for (int i = 0; i < 8; i++) {
                    float a = (&a4[i].x)[kk];
                    unsigned long long a2 = pack2(a, a);
                    fma2(acc[2 * i + 0], a2, b01);
                    fma2(acc[2 * i + 1], a2, b23);
                }
            }
        }
        __syncthreads();
    }

    #pragma unroll
    for (int i = 0; i < 8; i++) {
        int gr = m0 + ty * 8 + i;
        if (gr < N_NODES) {
            float2 lo = unpack2(acc[2 * i + 0]);
            float2 hi = unpack2(acc[2 * i + 1]);
            float4 o; o.x = lo.x; o.y = lo.y; o.z = hi.x; o.w = hi.y;
            *(float4*)&d_bufB[(size_t)gr * DIM + tx * 4] = o;
        }
    }
}

// ------ aggregation: bufA[c] = dinv2*bufB[c] + b + sum coef*bufB[src] -------
__global__ void __launch_bounds__(256) agg_kernel(const float* __restrict__ bias,
                                                  int do_relu) {
    int w = (blockIdx.x * blockDim.x + threadIdx.x) >> 5;
    if (w >= N_NODES) return;
    int lane = threadIdx.x & 31;
    int k = lane * 4;
    const float* h = (const float*)d_bufB;

    float4 hv = *(const float4*)&h[(size_t)w * DIM + k];
    float d2 = d_dinv2[w];
    float4 bb = *(const float4*)&bias[k];
    float4 acc;
    acc.x = d2 * hv.x + bb.x;
    acc.y = d2 * hv.y + bb.y;
    acc.z = d2 * hv.z + bb.z;
    acc.w = d2 * hv.w + bb.w;

    int e = d_off[w], end = d_off[w + 1];
    for (; e < end; e++) {
        int s   = __ldg(&d_src[e]);
        float c = __ldg(&d_coef[e]);
        float4 hs = *(const float4*)&h[(size_t)s * DIM + k];
        acc.x += c * hs.x;
        acc.y += c * hs.y;
        acc.z += c * hs.z;
        acc.w += c * hs.w;
    }
    if (do_relu) {
        acc.x = fmaxf(acc.x, 0.f);
        acc.y = fmaxf(acc.y, 0.f);
        acc.z = fmaxf(acc.z, 0.f);
        acc.w = fmaxf(acc.w, 0.f);
    }
    *(float4*)&d_bufA[(size_t)w * DIM + k] = acc;
}

// ---------------- pooling: atomic scatter into per-graph sums ----------------
__global__ void pool_kernel(const void* __restrict__ batch) {
    int t = blockIdx.x * blockDim.x + threadIdx.x;
    int node = t >> 5;
    if (node >= N_NODES) return;
    int lane = t & 31;
    int k = lane * 4;
    int g = load_idx(batch, node, d_idx64);
    float4 v = *(const float4*)&d_bufA[(size_t)node * DIM + k];
    atomicAdd(&d_sums[g * DIM + k + 0], v.x);
    atomicAdd(&d_sums[g * DIM + k + 1], v.y);
    atomicAdd(&d_sums[g * DIM + k + 2], v.z);
    atomicAdd(&d_sums[g * DIM + k + 3], v.w);
}

// ---------------- final FC: [512,128]/cnt @ [128,64] + bias ----------------
__global__ void fc_kernel(const float* __restrict__ Wfc,
                          const float* __restrict__ bfc,
                          float* __restrict__ out) {
    __shared__ float s[DIM];
    int g = blockIdx.x, t = threadIdx.x;  // 64 threads
    float inv = 1.0f / fmaxf(d_gcnt[g], 1.0f);
    s[t]      = d_sums[g * DIM + t] * inv;
    s[t + 64] = d_sums[g * DIM + 64 + t] * inv;
    __syncthreads();
    float acc = bfc[t];
    #pragma unroll
    for (int k = 0; k < DIM; k++) acc += s[k] * Wfc[k * OUT_DIM + t];
    out[g * OUT_DIM + t] = acc;
}

// ---------------- launch (ONLY kernel launches — no other CUDA API) --------
extern "C" void kernel_launch(void* const* d_in, const int* in_sizes, int n_in,
                              void* d_out, int out_size) {
    const float* x     = (const float*)d_in[0];
    const void*  ei    = d_in[1];
    const float* ew    = (const float*)d_in[2];
    const void*  batch = d_in[3];
    const float* W1 = (const float*)d_in[4];
    const float* b1 = (const float*)d_in[5];
    const float* W2 = (const float*)d_in[6];
    const float* b2 = (const float*)d_in[7];
    const float* W3 = (const float*)d_in[8];
    const float* b3 = (const float*)d_in[9];
    const float* W4 = (const float*)d_in[10];
    const float* b4 = (const float*)d_in[11];
    const float* Wfc = (const float*)d_in[12];
    const float* bfc = (const float*)d_in[13];
    float* out = (float*)d_out;

    const int EB = (N_EDGES + 255) / 256;     // 1954
    const int NB = (N_NODES + 255) / 256;     // 196
    const int GEMM_GRID = (N_NODES + 63) / 64;          // 782
    const int AGG_GRID  = (N_NODES * 32 + 255) / 256;   // 6250

    probe_kernel<<<1, 1>>>(ei);
    init_kernel<<<256, 256>>>();
    deg_kernel<<<EB, 256>>>(ei, ew);
    dinv_kernel<<<NB, 256>>>(batch);
    scan1_kernel<<<49, 1024>>>();
    scan2_kernel<<<1, 64>>>();
    scan3_kernel<<<NB, 256>>>();
    csr_fill_kernel<<<EB, 256>>>(ei, ew);

    gemm_kernel<<<GEMM_GRID, 256>>>(x, W1, 1);
    agg_kernel<<<AGG_GRID, 256>>>(b1, 1);

    gemm_kernel<<<GEMM_GRID, 256>>>(x, W2, 0);
    agg_kernel<<<AGG_GRID, 256>>>(b2, 1);

    gemm_kernel<<<GEMM_GRID, 256>>>(x, W3, 0);
    agg_kernel<<<AGG_GRID, 256>>>(b3, 1);

    gemm_kernel<<<GEMM_GRID, 256>>>(x, W4, 0);
    agg_kernel<<<AGG_GRID, 256>>>(b4, 0);

    pool_kernel<<<AGG_GRID, 256>>>(batch);
    fc_kernel<<<N_GRAPHS, 64>>>(Wfc, bfc, out);
}

// round 8
// speedup vs baseline: 1.2090x; 1.2090x over previous
#include <cuda_runtime.h>
#include <cuda_bf16.h>
#include <cstdint>

#define N_NODES 50000
#define N_EDGES 500000
#define DIM     128
#define OUT_DIM 64
#define N_GRAPHS 512

// ---------------- device scratch (static, allowed) ----------------
__device__ float d_bufA[N_NODES * DIM];   // activations (agg output)
__device__ float d_bufB[N_NODES * DIM];   // h = act @ W (gemm output)
__device__ float d_deg[N_NODES];
__device__ float d_dinv[N_NODES];
__device__ float d_dinv2[N_NODES];
__device__ int   d_count[N_NODES];
__device__ int   d_off[N_NODES + 1];
__device__ int   d_wp[N_NODES];
__device__ int   d_bsum[64];
__device__ int   d_src[N_EDGES];
__device__ float d_coef[N_EDGES];
__device__ float d_sums[N_GRAPHS * DIM];
__device__ float d_gcnt[N_GRAPHS];
__device__ int   d_idx64;                 // 1 if indices are int64, 0 if int32

// ---------------- index dtype probe + dual-path accessor ----------------
__global__ void probe_kernel(const void* __restrict__ ei) {
    const long long* p = (const long long*)ei;
    int ok = 0;
    for (int i = 0; i < 16; i++) {
        long long v = p[i];
        if (v >= 0 && v < N_NODES) ok++;
    }
    d_idx64 = (ok >= 15) ? 1 : 0;
}

__device__ __forceinline__ int load_idx(const void* __restrict__ p, int i, int is64) {
    if (is64) return (int)((const long long*)p)[i];
    return ((const int*)p)[i];
}

// ---------------- tf32 helpers ----------------
__device__ __forceinline__ unsigned cvt_tf32(float f) {
    unsigned u;
    asm("cvt.rna.tf32.f32 %0, %1;" : "=r"(u) : "f"(f));
    return u;
}
__device__ __forceinline__ void mma_tf32(float4& d, const unsigned* a, const unsigned* b) {
    asm volatile(
        "mma.sync.aligned.m16n8k8.row.col.f32.tf32.tf32.f32 "
        "{%0,%1,%2,%3}, {%4,%5,%6,%7}, {%8,%9}, {%0,%1,%2,%3};\n"
        : "+f"(d.x), "+f"(d.y), "+f"(d.z), "+f"(d.w)
        : "r"(a[0]), "r"(a[1]), "r"(a[2]), "r"(a[3]), "r"(b[0]), "r"(b[1]));
}

// ---------------- init: deg=1 (self loop), counters=0 ----------------
__global__ void init_kernel() {
    int i = blockIdx.x * blockDim.x + threadIdx.x;
    if (i < N_NODES) { d_deg[i] = 1.0f; d_count[i] = 0; }
    if (i < N_GRAPHS * DIM) d_sums[i] = 0.0f;
    if (i < N_GRAPHS) d_gcnt[i] = 0.0f;
}

// ---------------- degree + in-edge histogram ----------------
__global__ void deg_kernel(const void* __restrict__ ei,
                           const float* __restrict__ ew) {
    int e = blockIdx.x * blockDim.x + threadIdx.x;
    if (e >= N_EDGES) return;
    int is64 = d_idx64;
    int c = load_idx(ei, N_EDGES + e, is64);
    atomicAdd(&d_deg[c], ew[e]);
    atomicAdd(&d_count[c], 1);
}

// ---------------- dinv + per-graph node counts ----------------
__global__ void dinv_kernel(const void* __restrict__ batch) {
    int i = blockIdx.x * blockDim.x + threadIdx.x;
    if (i >= N_NODES) return;
    int is64 = d_idx64;
    float d  = d_deg[i];
    float di = rsqrtf(d);
    d_dinv[i]  = di;
    d_dinv2[i] = di * di;
    atomicAdd(&d_gcnt[load_idx(batch, i, is64)], 1.0f);
}

// ---------------- 3-phase exclusive scan of d_count -> d_off ----------------
__global__ void scan1_kernel() {   // 49 blocks x 1024
    __shared__ int wsum[32];
    int tid = threadIdx.x;
    int i = blockIdx.x * 1024 + tid;
    int v = (i < N_NODES) ? d_count[i] : 0;
    int lane = tid & 31, wid = tid >> 5;
    int s = v;
    #pragma unroll
    for (int o = 1; o < 32; o <<= 1) {
        int t = __shfl_up_sync(0xFFFFFFFFu, s, o);
        if (lane >= o) s += t;
    }
    if (lane == 31) wsum[wid] = s;
    __syncthreads();
    if (wid == 0) {
        int ws = wsum[lane];
        int orig = ws;
        #pragma unroll
        for (int o = 1; o < 32; o <<= 1) {
            int t = __shfl_up_sync(0xFFFFFFFFu, ws, o);
            if (lane >= o) ws += t;
        }
        wsum[lane] = ws - orig;   // exclusive warp offsets
    }
    __syncthreads();
    int excl = s - v + wsum[wid];
    if (i < N_NODES) d_off[i] = excl;
    if (tid == 1023) d_bsum[blockIdx.x] = s + wsum[wid]; // block total
}

__global__ void scan2_kernel() {   // 1 block x 64
    __shared__ int sh[64];
    int tid = threadIdx.x;
    int v = (tid < 49) ? d_bsum[tid] : 0;
    sh[tid] = v;
    __syncthreads();
    for (int o = 1; o < 64; o <<= 1) {
        int t = (tid >= o) ? sh[tid - o] : 0;
        __syncthreads();
        sh[tid] += t;
        __syncthreads();
    }
    if (tid < 49) d_bsum[tid] = sh[tid] - v;  // exclusive
}

__global__ void scan3_kernel() {
    int i = blockIdx.x * blockDim.x + threadIdx.x;
    if (i < N_NODES) {
        int o = d_off[i] + d_bsum[i >> 10];
        d_off[i] = o;
        d_wp[i]  = o;
    }
    if (i == 0) d_off[N_NODES] = N_EDGES;
}

// ---------------- CSR fill: (src, coef) per destination ----------------
__global__ void csr_fill_kernel(const void* __restrict__ ei,
                                const float* __restrict__ ew) {
    int e = blockIdx.x * blockDim.x + threadIdx.x;
    if (e >= N_EDGES) return;
    int is64 = d_idx64;
    int r = load_idx(ei, e, is64);
    int c = load_idx(ei, N_EDGES + e, is64);
    int p = atomicAdd(&d_wp[c], 1);
    d_src[p]  = r;
    d_coef[p] = ew[e] * d_dinv[r] * d_dinv[c];
}

// ---------------- GEMM (tf32 tensor cores): d_bufB = A @ W ------------------
// A = (use_ext ? Xext : d_bufA). BM=128, BN=128, K chunked 4x32.
// 8 warps: 4(m) x 2(n); warp tile 32(m) x 64(n).
#define AS_STRIDE 36
#define WS_STRIDE 132
__global__ void __launch_bounds__(256, 2) gemm_kernel(const float* __restrict__ Xext,
                                                      const float* __restrict__ W,
                                                      int use_ext) {
    __shared__ float As[128 * AS_STRIDE];   // 18KB, tf32 bits
    __shared__ float Ws[32 * WS_STRIDE];    // 16.9KB, tf32 bits
    const float* A = use_ext ? Xext : (const float*)d_bufA;

    int tid  = threadIdx.x;
    int warp = tid >> 5, lane = tid & 31;
    int wm = warp >> 1, wn = warp & 1;
    int m0 = blockIdx.x * 128;
    int grp = lane >> 2, tig = lane & 3;   // groupID, threadID-in-group

    float4 acc[2][8];
    #pragma unroll
    for (int t = 0; t < 2; t++)
        #pragma unroll
        for (int n = 0; n < 8; n++)
            acc[t][n] = make_float4(0.f, 0.f, 0.f, 0.f);

    #pragma unroll
    for (int kc = 0; kc < 4; kc++) {
        // W chunk: rows kc*32..+31, 128 cols (1024 float4), cvt to tf32 bits
        #pragma unroll
        for (int it = 0; it < 4; it++) {
            int idx = tid + it * 256;
            int k = idx >> 5, n4 = idx & 31;
            float4 w = *(const float4*)&W[(kc * 32 + k) * DIM + n4 * 4];
            unsigned* ws = (unsigned*)&Ws[k * WS_STRIDE + n4 * 4];
            uint4 t4;
            t4.x = cvt_tf32(w.x); t4.y = cvt_tf32(w.y);
            t4.z = cvt_tf32(w.z); t4.w = cvt_tf32(w.w);
            *(uint4*)ws = t4;
        }
        // A chunk: 128 rows x 32 k (1024 float4)
        #pragma unroll
        for (int it = 0; it < 4; it++) {
            int idx = tid + it * 256;
            int r = idx >> 3, c4 = idx & 7;
            int gr = m0 + r;
            float4 a = make_float4(0.f, 0.f, 0.f, 0.f);
            if (gr < N_NODES)
                a = *(const float4*)&A[(size_t)gr * DIM + kc * 32 + c4 * 4];
            uint4 t4;
            t4.x = cvt_tf32(a.x); t4.y = cvt_tf32(a.y);
            t4.z = cvt_tf32(a.z); t4.w = cvt_tf32(a.w);
            *(uint4*)&As[r * AS_STRIDE + c4 * 4] = t4;
        }
        __syncthreads();

        #pragma unroll
        for (int ks = 0; ks < 4; ks++) {
            int k0 = ks * 8;
            unsigned af[2][4];
            #pragma unroll
            for (int t = 0; t < 2; t++) {
                int row = wm * 32 + t * 16 + grp;
                const unsigned* as = (const unsigned*)As;
                af[t][0] = as[(row    ) * AS_STRIDE + k0 + tig    ];
                af[t][1] = as[(row + 8) * AS_STRIDE + k0 + tig    ];
                af[t][2] = as[(row    ) * AS_STRIDE + k0 + tig + 4];
                af[t][3] = as[(row + 8) * AS_STRIDE + k0 + tig + 4];
            }
            unsigned bf[8][2];
            #pragma unroll
            for (int nt = 0; nt < 8; nt++) {
                int n = wn * 64 + nt * 8 + grp;
                const unsigned* ws = (const unsigned*)Ws;
                bf[nt][0] = ws[(k0 + tig    ) * WS_STRIDE + n];
                bf[nt][1] = ws[(k0 + tig + 4) * WS_STRIDE + n];
            }
            #pragma unroll
            for (int t = 0; t < 2; t++)
                #pragma unroll
                for (int nt = 0; nt < 8; nt++)
                    mma_tf32(acc[t][nt], af[t], bf[nt]);
        }
        __syncthreads();
    }

    // epilogue: per tile, c0/c1 at (row, col..col+1), c2/c3 at (row+8, ...)
    #pragma unroll
    for (int t = 0; t < 2; t++) {
        int row = m0 + wm * 32 + t * 16 + grp;
        #pragma unroll
        for (int nt = 0; nt < 8; nt++) {
            int col = wn * 64 + nt * 8 + 2 * tig;
            if (row < N_NODES) {
                float2 v = make_float2(acc[t][nt].x, acc[t][nt].y);
                *(float2*)&d_bufB[(size_t)row * DIM + col] = v;
            }
            if (row + 8 < N_NODES) {
                float2 v = make_float2(acc[t][nt].z, acc[t][nt].w);
                *(float2*)&d_bufB[(size_t)(row + 8) * DIM + col] = v;
            }
        }
    }
}

// ------ aggregation: bufA[c] = dinv2*bufB[c] + b + sum coef*bufB[src] -------
__global__ void __launch_bounds__(256) agg_kernel(const float* __restrict__ bias,
                                                  int do_relu) {
    int w = (blockIdx.x * blockDim.x + threadIdx.x) >> 5;
    if (w >= N_NODES) return;
    int lane = threadIdx.x & 31;
    int k = lane * 4;
    const float* h = (const float*)d_bufB;

    float4 hv = *(const float4*)&h[(size_t)w * DIM + k];
    float d2 = d_dinv2[w];
    float4 bb = *(const float4*)&bias[k];
    float4 acc;
    acc.x = d2 * hv.x + bb.x;
    acc.y = d2 * hv.y + bb.y;
    acc.z = d2 * hv.z + bb.z;
    acc.w = d2 * hv.w + bb.w;

    int e = d_off[w], end = d_off[w + 1];
    for (; e < end; e++) {
        int s   = __ldg(&d_src[e]);
        float c = __ldg(&d_coef[e]);
        float4 hs = *(const float4*)&h[(size_t)s * DIM + k];
        acc.x += c * hs.x;
        acc.y += c * hs.y;
        acc.z += c * hs.z;
        acc.w += c * hs.w;
    }
    if (do_relu) {
        acc.x = fmaxf(acc.x, 0.f);
        acc.y = fmaxf(acc.y, 0.f);
        acc.z = fmaxf(acc.z, 0.f);
        acc.w = fmaxf(acc.w, 0.f);
    }
    *(float4*)&d_bufA[(size_t)w * DIM + k] = acc;
}

// ---------------- pooling: atomic scatter into per-graph sums ----------------
__global__ void pool_kernel(const void* __restrict__ batch) {
    int t = blockIdx.x * blockDim.x + threadIdx.x;
    int node = t >> 5;
    if (node >= N_NODES) return;
    int lane = t & 31;
    int k = lane * 4;
    int g = load_idx(batch, node, d_idx64);
    float4 v = *(const float4*)&d_bufA[(size_t)node * DIM + k];
    atomicAdd(&d_sums[g * DIM + k + 0], v.x);
    atomicAdd(&d_sums[g * DIM + k + 1], v.y);
    atomicAdd(&d_sums[g * DIM + k + 2], v.z);
    atomicAdd(&d_sums[g * DIM + k + 3], v.w);
}

// ---------------- final FC: [512,128]/cnt @ [128,64] + bias ----------------
__global__ void fc_kernel(const float* __restrict__ Wfc,
                          const float* __restrict__ bfc,
                          float* __restrict__ out) {
    __shared__ float s[DIM];
    int g = blockIdx.x, t = threadIdx.x;  // 64 threads
    float inv = 1.0f / fmaxf(d_gcnt[g], 1.0f);
    s[t]      = d_sums[g * DIM + t] * inv;
    s[t + 64] = d_sums[g * DIM + 64 + t] * inv;
    __syncthreads();
    float acc = bfc[t];
    #pragma unroll
    for (int k = 0; k < DIM; k++) acc += s[k] * Wfc[k * OUT_DIM + t];
    out[g * OUT_DIM + t] = acc;
}

// ---------------- launch (ONLY kernel launches — no other CUDA API) --------
extern "C" void kernel_launch(void* const* d_in, const int* in_sizes, int n_in,
                              void* d_out, int out_size) {
    const float* x     = (const float*)d_in[0];
    const void*  ei    = d_in[1];
    const float* ew    = (const float*)d_in[2];
    const void*  batch = d_in[3];
    const float* W1 = (const float*)d_in[4];
    const float* b1 = (const float*)d_in[5];
    const float* W2 = (const float*)d_in[6];
    const float* b2 = (const float*)d_in[7];
    const float* W3 = (const float*)d_in[8];
    const float* b3 = (const float*)d_in[9];
    const float* W4 = (const float*)d_in[10];
    const float* b4 = (const float*)d_in[11];
    const float* Wfc = (const float*)d_in[12];
    const float* bfc = (const float*)d_in[13];
    float* out = (float*)d_out;

    const int EB = (N_EDGES + 255) / 256;     // 1954
    const int NB = (N_NODES + 255) / 256;     // 196
    const int GEMM_GRID = (N_NODES + 127) / 128;        // 391
    const int AGG_GRID  = (N_NODES * 32 + 255) / 256;   // 6250

    probe_kernel<<<1, 1>>>(ei);
    init_kernel<<<256, 256>>>();
    deg_kernel<<<EB, 256>>>(ei, ew);
    dinv_kernel<<<NB, 256>>>(batch);
    scan1_kernel<<<49, 1024>>>();
    scan2_kernel<<<1, 64>>>();
    scan3_kernel<<<NB, 256>>>();
    csr_fill_kernel<<<EB, 256>>>(ei, ew);

    gemm_kernel<<<GEMM_GRID, 256>>>(x, W1, 1);
    agg_kernel<<<AGG_GRID, 256>>>(b1, 1);

    gemm_kernel<<<GEMM_GRID, 256>>>(x, W2, 0);
    agg_kernel<<<AGG_GRID, 256>>>(b2, 1);

    gemm_kernel<<<GEMM_GRID, 256>>>(x, W3, 0);
    agg_kernel<<<AGG_GRID, 256>>>(b3, 1);

    gemm_kernel<<<GEMM_GRID, 256>>>(x, W4, 0);
    agg_kernel<<<AGG_GRID, 256>>>(b4, 0);

    pool_kernel<<<AGG_GRID, 256>>>(batch);
    fc_kernel<<<N_GRAPHS, 64>>>(Wfc, bfc, out);
}

// round 10
// speedup vs baseline: 1.3999x; 1.1580x over previous
#include <cuda_runtime.h>
#include <cuda_bf16.h>
#include <cstdint>

#define N_NODES 50000
#define N_EDGES 500000
#define DIM     128
#define OUT_DIM 64
#define N_GRAPHS 512

// ---------------- device scratch (static, allowed) ----------------
__device__ float d_bufA[N_NODES * DIM];   // activations (agg output)
__device__ float d_bufB[N_NODES * DIM];   // h = act @ W (gemm output)
__device__ float d_deg[N_NODES];
__device__ float d_dinv[N_NODES];
__device__ float d_dinv2[N_NODES];
__device__ int   d_count[N_NODES];
__device__ int   d_off[N_NODES + 1];
__device__ int   d_wp[N_NODES];
__device__ int   d_bsum[64];
__device__ int   d_src[N_EDGES];
__device__ float d_coef[N_EDGES];
__device__ int   d_goff[N_GRAPHS + 1];
__device__ int   d_idx64;                 // 1 if indices are int64, 0 if int32

__device__ __forceinline__ int load_idx(const void* __restrict__ p, int i, int is64) {
    if (is64) return (int)((const long long*)p)[i];
    return ((const int*)p)[i];
}

// ---------------- tf32 helpers ----------------
__device__ __forceinline__ unsigned cvt_tf32(float f) {
    unsigned u;
    asm("cvt.rna.tf32.f32 %0, %1;" : "=r"(u) : "f"(f));
    return u;
}
__device__ __forceinline__ void mma_tf32(float4& d, const unsigned* a, const unsigned* b) {
    asm volatile(
        "mma.sync.aligned.m16n8k8.row.col.f32.tf32.tf32.f32 "
        "{%0,%1,%2,%3}, {%4,%5,%6,%7}, {%8,%9}, {%0,%1,%2,%3};\n"
        : "+f"(d.x), "+f"(d.y), "+f"(d.z), "+f"(d.w)
        : "r"(a[0]), "r"(a[1]), "r"(a[2]), "r"(a[3]), "r"(b[0]), "r"(b[1]));
}

// ---------------- init (probe merged): deg=1, count=0 ----------------
__global__ void init_kernel(const void* __restrict__ ei) {
    int i = blockIdx.x * blockDim.x + threadIdx.x;
    if (i == 0) {
        // dtype probe: int64 data has first 16 values in [0, N_NODES)
        const long long* p = (const long long*)ei;
        int ok = 0;
        for (int j = 0; j < 16; j++) {
            long long v = p[j];
            if (v >= 0 && v < N_NODES) ok++;
        }
        d_idx64 = (ok >= 15) ? 1 : 0;
    }
    if (i < N_NODES) { d_deg[i] = 1.0f; d_count[i] = 0; }
}

// ---------------- graph offsets from sorted batch (no atomics) --------------
__global__ void goff_kernel(const void* __restrict__ batch) {
    int i = blockIdx.x * blockDim.x + threadIdx.x;
    if (i >= N_NODES) return;
    int is64 = d_idx64;
    int b = load_idx(batch, i, is64);
    if (i == 0) {
        for (int g = 0; g <= b; g++) d_goff[g] = 0;
    } else {
        int pb = load_idx(batch, i - 1, is64);
        for (int g = pb + 1; g <= b; g++) d_goff[g] = i;
    }
    if (i == N_NODES - 1) {
        for (int g = b + 1; g <= N_GRAPHS; g++) d_goff[g] = N_NODES;
    }
}

// ---------------- degree + in-edge histogram ----------------
__global__ void deg_kernel(const void* __restrict__ ei,
                           const float* __restrict__ ew) {
    int e = blockIdx.x * blockDim.x + threadIdx.x;
    if (e >= N_EDGES) return;
    int is64 = d_idx64;
    int c = load_idx(ei, N_EDGES + e, is64);
    atomicAdd(&d_deg[c], ew[e]);
    atomicAdd(&d_count[c], 1);
}

// ---------------- 3-phase exclusive scan of d_count -> d_off ----------------
__global__ void scan1_kernel() {   // 49 blocks x 1024
    __shared__ int wsum[32];
    int tid = threadIdx.x;
    int i = blockIdx.x * 1024 + tid;
    int v = (i < N_NODES) ? d_count[i] : 0;
    int lane = tid & 31, wid = tid >> 5;
    int s = v;
    #pragma unroll
    for (int o = 1; o < 32; o <<= 1) {
        int t = __shfl_up_sync(0xFFFFFFFFu, s, o);
        if (lane >= o) s += t;
    }
    if (lane == 31) wsum[wid] = s;
    __syncthreads();
    if (wid == 0) {
        int ws = wsum[lane];
        int orig = ws;
        #pragma unroll
        for (int o = 1; o < 32; o <<= 1) {
            int t = __shfl_up_sync(0xFFFFFFFFu, ws, o);
            if (lane >= o) ws += t;
        }
        wsum[lane] = ws - orig;   // exclusive warp offsets
    }
    __syncthreads();
    int excl = s - v + wsum[wid];
    if (i < N_NODES) d_off[i] = excl;
    if (tid == 1023) d_bsum[blockIdx.x] = s + wsum[wid]; // block total
}

__global__ void scan2_kernel() {   // 1 block x 64
    __shared__ int sh[64];
    int tid = threadIdx.x;
    int v = (tid < 49) ? d_bsum[tid] : 0;
    sh[tid] = v;
    __syncthreads();
    for (int o = 1; o < 64; o <<= 1) {
        int t = (tid >= o) ? sh[tid - o] : 0;
        __syncthreads();
        sh[tid] += t;
        __syncthreads();
    }
    if (tid < 49) d_bsum[tid] = sh[tid] - v;  // exclusive
}

// scan3 + dinv merged (node-wise pass)
__global__ void scan3_kernel() {
    int i = blockIdx.x * blockDim.x + threadIdx.x;
    if (i < N_NODES) {
        int o = d_off[i] + d_bsum[i >> 10];
        d_off[i] = o;
        d_wp[i]  = o;
        float di = rsqrtf(d_deg[i]);   // deg >= 1 always (self loop)
        d_dinv[i]  = di;
        d_dinv2[i] = di * di;
    }
    if (i == 0) d_off[N_NODES] = N_EDGES;
}

// ---------------- CSR fill: (src, coef) per destination ----------------
__global__ void csr_fill_kernel(const void* __restrict__ ei,
                                const float* __restrict__ ew) {
    int e = blockIdx.x * blockDim.x + threadIdx.x;
    if (e >= N_EDGES) return;
    int is64 = d_idx64;
    int r = load_idx(ei, e, is64);
    int c = load_idx(ei, N_EDGES + e, is64);
    int p = atomicAdd(&d_wp[c], 1);
    d_src[p]  = r;
    d_coef[p] = ew[e] * d_dinv[r] * d_dinv[c];
}

// ---------------- GEMM (tf32 tensor cores): d_bufB = A @ W ------------------
#define AS_STRIDE 36
#define WS_STRIDE 132
__global__ void __launch_bounds__(256, 2) gemm_kernel(const float* __restrict__ Xext,
                                                      const float* __restrict__ W,
                                                      int use_ext) {
    __shared__ float As[128 * AS_STRIDE];   // 18KB, tf32 bits
    __shared__ float Ws[32 * WS_STRIDE];    // 16.9KB, tf32 bits
    const float* A = use_ext ? Xext : (const float*)d_bufA;

    int tid  = threadIdx.x;
    int warp = tid >> 5, lane = tid & 31;
    int wm = warp >> 1, wn = warp & 1;
    int m0 = blockIdx.x * 128;
    int grp = lane >> 2, tig = lane & 3;   // groupID, threadID-in-group

    float4 acc[2][8];
    #pragma unroll
    for (int t = 0; t < 2; t++)
        #pragma unroll
        for (int n = 0; n < 8; n++)
            acc[t][n] = make_float4(0.f, 0.f, 0.f, 0.f);

    #pragma unroll
    for (int kc = 0; kc < 4; kc++) {
        #pragma unroll
        for (int it = 0; it < 4; it++) {
            int idx = tid + it * 256;
            int k = idx >> 5, n4 = idx & 31;
            float4 w = *(const float4*)&W[(kc * 32 + k) * DIM + n4 * 4];
            unsigned* ws = (unsigned*)&Ws[k * WS_STRIDE + n4 * 4];
            uint4 t4;
            t4.x = cvt_tf32(w.x); t4.y = cvt_tf32(w.y);
            t4.z = cvt_tf32(w.z); t4.w = cvt_tf32(w.w);
            *(uint4*)ws = t4;
        }
        #pragma unroll
        for (int it = 0; it < 4; it++) {
            int idx = tid + it * 256;
            int r = idx >> 3, c4 = idx & 7;
            int gr = m0 + r;
            float4 a = make_float4(0.f, 0.f, 0.f, 0.f);
            if (gr < N_NODES)
                a = *(const float4*)&A[(size_t)gr * DIM + kc * 32 + c4 * 4];
            uint4 t4;
            t4.x = cvt_tf32(a.x); t4.y = cvt_tf32(a.y);
            t4.z = cvt_tf32(a.z); t4.w = cvt_tf32(a.w);
            *(uint4*)&As[r * AS_STRIDE + c4 * 4] = t4;
        }
        __syncthreads();

        #pragma unroll
        for (int ks = 0; ks < 4; ks++) {
            int k0 = ks * 8;
            unsigned af[2][4];
            #pragma unroll
            for (int t = 0; t < 2; t++) {
                int row = wm * 32 + t * 16 + grp;
                const unsigned* as = (const unsigned*)As;
                af[t][0] = as[(row    ) * AS_STRIDE + k0 + tig    ];
                af[t][1] = as[(row + 8) * AS_STRIDE + k0 + tig    ];
                af[t][2] = as[(row    ) * AS_STRIDE + k0 + tig + 4];
                af[t][3] = as[(row + 8) * AS_STRIDE + k0 + tig + 4];
            }
            unsigned bf[8][2];
            #pragma unroll
            for (int nt = 0; nt < 8; nt++) {
                int n = wn * 64 + nt * 8 + grp;
                const unsigned* ws = (const unsigned*)Ws;
                bf[nt][0] = ws[(k0 + tig    ) * WS_STRIDE + n];
                bf[nt][1] = ws[(k0 + tig + 4) * WS_STRIDE + n];
            }
            #pragma unroll
            for (int t = 0; t < 2; t++)
                #pragma unroll
                for (int nt = 0; nt < 8; nt++)
                    mma_tf32(acc[t][nt], af[t], bf[nt]);
        }
        __syncthreads();
    }

    #pragma unroll
    for (int t = 0; t < 2; t++) {
        int row = m0 + wm * 32 + t * 16 + grp;
        #pragma unroll
        for (int nt = 0; nt < 8; nt++) {
            int col = wn * 64 + nt * 8 + 2 * tig;
            if (row < N_NODES) {
                float2 v = make_float2(acc[t][nt].x, acc[t][nt].y);
                *(float2*)&d_bufB[(size_t)row * DIM + col] = v;
            }
            if (row + 8 < N_NODES) {
                float2 v = make_float2(acc[t][nt].z, acc[t][nt].w);
                *(float2*)&d_bufB[(size_t)(row + 8) * DIM + col] = v;
            }
        }
    }
}

// ------ aggregation: bufA[c] = dinv2*bufB[c] + b + sum coef*bufB[src] -------
__global__ void __launch_bounds__(256) agg_kernel(const float* __restrict__ bias,
                                                  int do_relu) {
    int w = (blockIdx.x * blockDim.x + threadIdx.x) >> 5;
    if (w >= N_NODES) return;
    int lane = threadIdx.x & 31;
    int k = lane * 4;
    const float* h = (const float*)d_bufB;

    float4 hv = *(const float4*)&h[(size_t)w * DIM + k];
    float d2 = d_dinv2[w];
    float4 bb = *(const float4*)&bias[k];
    float4 acc;
    acc.x = d2 * hv.x + bb.x;
    acc.y = d2 * hv.y + bb.y;
    acc.z = d2 * hv.z + bb.z;
    acc.w = d2 * hv.w + bb.w;

    int e = d_off[w], end = d_off[w + 1];
    for (; e < end; e++) {
        int s   = __ldg(&d_src[e]);
        float c = __ldg(&d_coef[e]);
        float4 hs = *(const float4*)&h[(size_t)s * DIM + k];
        acc.x += c * hs.x;
        acc.y += c * hs.y;
        acc.z += c * hs.z;
        acc.w += c * hs.w;
    }
    if (do_relu) {
        acc.x = fmaxf(acc.x, 0.f);
        acc.y = fmaxf(acc.y, 0.f);
        acc.z = fmaxf(acc.z, 0.f);
        acc.w = fmaxf(acc.w, 0.f);
    }
    *(float4*)&d_bufA[(size_t)w * DIM + k] = acc;
}

// ------------- fused segmented mean-pool + FC (one block per graph) ---------
__global__ void __launch_bounds__(128) pool_fc_kernel(const float* __restrict__ Wfc,
                                                      const float* __restrict__ bfc,
                                                      float* __restrict__ out) {
    __shared__ float pooled[DIM];
    int g = blockIdx.x, t = threadIdx.x;   // 128 threads
    int s0 = d_goff[g], s1 = d_goff[g + 1];
    float sum = 0.0f;
    for (int n = s0; n < s1; n++)
        sum += d_bufA[(size_t)n * DIM + t];
    float inv = 1.0f / fmaxf((float)(s1 - s0), 1.0f);
    pooled[t] = sum * inv;
    __syncthreads();
    if (t < OUT_DIM) {
        float acc = bfc[t];
        #pragma unroll
        for (int k = 0; k < DIM; k++)
            acc += pooled[k] * Wfc[k * OUT_DIM + t];
        out[g * OUT_DIM + t] = acc;
    }
}

// ---------------- launch (ONLY kernel launches — no other CUDA API) --------
extern "C" void kernel_launch(void* const* d_in, const int* in_sizes, int n_in,
                              void* d_out, int out_size) {
    const float* x     = (const float*)d_in[0];
    const void*  ei    = d_in[1];
    const float* ew    = (const float*)d_in[2];
    const void*  batch = d_in[3];
    const float* W1 = (const float*)d_in[4];
    const float* b1 = (const float*)d_in[5];
    const float* W2 = (const float*)d_in[6];
    const float* b2 = (const float*)d_in[7];
    const float* W3 = (const float*)d_in[8];
    const float* b3 = (const float*)d_in[9];
    const float* W4 = (const float*)d_in[10];
    const float* b4 = (const float*)d_in[11];
    const float* Wfc = (const float*)d_in[12];
    const float* bfc = (const float*)d_in[13];
    float* out = (float*)d_out;

    const int EB = (N_EDGES + 255) / 256;     // 1954
    const int NB = (N_NODES + 255) / 256;     // 196
    const int GEMM_GRID = (N_NODES + 127) / 128;        // 391
    const int AGG_GRID  = (N_NODES * 32 + 255) / 256;   // 6250

    init_kernel<<<NB, 256>>>(ei);
    goff_kernel<<<NB, 256>>>(batch);
    deg_kernel<<<EB, 256>>>(ei, ew);
    scan1_kernel<<<49, 1024>>>();
    scan2_kernel<<<1, 64>>>();
    scan3_kernel<<<NB, 256>>>();
    csr_fill_kernel<<<EB, 256>>>(ei, ew);

    gemm_kernel<<<GEMM_GRID, 256>>>(x, W1, 1);
    agg_kernel<<<AGG_GRID, 256>>>(b1, 1);

    gemm_kernel<<<GEMM_GRID, 256>>>(x, W2, 0);
    agg_kernel<<<AGG_GRID, 256>>>(b2, 1);

    gemm_kernel<<<GEMM_GRID, 256>>>(x, W3, 0);
    agg_kernel<<<AGG_GRID, 256>>>(b3, 1);

    gemm_kernel<<<GEMM_GRID, 256>>>(x, W4, 0);
    agg_kernel<<<AGG_GRID, 256>>>(b4, 0);

    pool_fc_kernel<<<N_GRAPHS, 128>>>(Wfc, bfc, out);
}

// round 12
// speedup vs baseline: 1.4965x; 1.0690x over previous
#include <cuda_runtime.h>
#include <cuda_bf16.h>
#include <cstdint>

#define N_NODES 50000
#define N_EDGES 500000
#define DIM     128
#define OUT_DIM 64
#define N_GRAPHS 512

// ---------------- device scratch (static, allowed) ----------------
__device__ float    d_bufA[N_NODES * DIM];   // activations (agg output, fp32)
__device__ unsigned d_bufB16[N_NODES * 64];  // h = act @ W, bf16x2 packed
__device__ float d_deg[N_NODES];
__device__ float d_dinv[N_NODES];
__device__ float d_dinv2[N_NODES];
__device__ int   d_count[N_NODES];
__device__ int   d_off[N_NODES + 1];
__device__ int   d_wp[N_NODES];
__device__ int   d_bsum[64];
__device__ int   d_src[N_EDGES];
__device__ float d_coef[N_EDGES];
__device__ int   d_goff[N_GRAPHS + 1];
__device__ int   d_idx64;                 // 1 if indices are int64, 0 if int32

__device__ __forceinline__ int load_idx(const void* __restrict__ p, int i, int is64) {
    if (is64) return (int)((const long long*)p)[i];
    return ((const int*)p)[i];
}

// ---------------- tf32 helpers ----------------
__device__ __forceinline__ unsigned cvt_tf32(float f) {
    unsigned u;
    asm("cvt.rna.tf32.f32 %0, %1;" : "=r"(u) : "f"(f));
    return u;
}
__device__ __forceinline__ void mma_tf32(float4& d, const unsigned* a, const unsigned* b) {
    asm volatile(
        "mma.sync.aligned.m16n8k8.row.col.f32.tf32.tf32.f32 "
        "{%0,%1,%2,%3}, {%4,%5,%6,%7}, {%8,%9}, {%0,%1,%2,%3};\n"
        : "+f"(d.x), "+f"(d.y), "+f"(d.z), "+f"(d.w)
        : "r"(a[0]), "r"(a[1]), "r"(a[2]), "r"(a[3]), "r"(b[0]), "r"(b[1]));
}

// ---------------- init (probe merged): deg=1, count=0 ----------------
__global__ void init_kernel(const void* __restrict__ ei) {
    int i = blockIdx.x * blockDim.x + threadIdx.x;
    if (i == 0) {
        const long long* p = (const long long*)ei;
        int ok = 0;
        for (int j = 0; j < 16; j++) {
            long long v = p[j];
            if (v >= 0 && v < N_NODES) ok++;
        }
        d_idx64 = (ok >= 15) ? 1 : 0;
    }
    if (i < N_NODES) { d_deg[i] = 1.0f; d_count[i] = 0; }
}

// ---------------- graph offsets from sorted batch (no atomics) --------------
__global__ void goff_kernel(const void* __restrict__ batch) {
    int i = blockIdx.x * blockDim.x + threadIdx.x;
    if (i >= N_NODES) return;
    int is64 = d_idx64;
    int b = load_idx(batch, i, is64);
    if (i == 0) {
        for (int g = 0; g <= b; g++) d_goff[g] = 0;
    } else {
        int pb = load_idx(batch, i - 1, is64);
        for (int g = pb + 1; g <= b; g++) d_goff[g] = i;
    }
    if (i == N_NODES - 1) {
        for (int g = b + 1; g <= N_GRAPHS; g++) d_goff[g] = N_NODES;
    }
}

// ---------------- degree + in-edge histogram ----------------
__global__ void deg_kernel(const void* __restrict__ ei,
                           const float* __restrict__ ew) {
    int e = blockIdx.x * blockDim.x + threadIdx.x;
    if (e >= N_EDGES) return;
    int is64 = d_idx64;
    int c = load_idx(ei, N_EDGES + e, is64);
    atomicAdd(&d_deg[c], ew[e]);
    atomicAdd(&d_count[c], 1);
}

// ---------------- 3-phase exclusive scan of d_count -> d_off ----------------
__global__ void scan1_kernel() {   // 49 blocks x 1024
    __shared__ int wsum[32];
    int tid = threadIdx.x;
    int i = blockIdx.x * 1024 + tid;
    int v = (i < N_NODES) ? d_count[i] : 0;
    int lane = tid & 31, wid = tid >> 5;
    int s = v;
    #pragma unroll
    for (int o = 1; o < 32; o <<= 1) {
        int t = __shfl_up_sync(0xFFFFFFFFu, s, o);
        if (lane >= o) s += t;
    }
    if (lane == 31) wsum[wid] = s;
    __syncthreads();
    if (wid == 0) {
        int ws = wsum[lane];
        int orig = ws;
        #pragma unroll
        for (int o = 1; o < 32; o <<= 1) {
            int t = __shfl_up_sync(0xFFFFFFFFu, ws, o);
            if (lane >= o) ws += t;
        }
        wsum[lane] = ws - orig;   // exclusive warp offsets
    }
    __syncthreads();
    int excl = s - v + wsum[wid];
    if (i < N_NODES) d_off[i] = excl;
    if (tid == 1023) d_bsum[blockIdx.x] = s + wsum[wid]; // block total
}

__global__ void scan2_kernel() {   // 1 block x 64
    __shared__ int sh[64];
    int tid = threadIdx.x;
    int v = (tid < 49) ? d_bsum[tid] : 0;
    sh[tid] = v;
    __syncthreads();
    for (int o = 1; o < 64; o <<= 1) {
        int t = (tid >= o) ? sh[tid - o] : 0;
        __syncthreads();
        sh[tid] += t;
        __syncthreads();
    }
    if (tid < 49) d_bsum[tid] = sh[tid] - v;  // exclusive
}

// scan3 + dinv merged (node-wise pass)
__global__ void scan3_kernel() {
    int i = blockIdx.x * blockDim.x + threadIdx.x;
    if (i < N_NODES) {
        int o = d_off[i] + d_bsum[i >> 10];
        d_off[i] = o;
        d_wp[i]  = o;
        float di = rsqrtf(d_deg[i]);   // deg >= 1 always (self loop)
        d_dinv[i]  = di;
        d_dinv2[i] = di * di;
    }
    if (i == 0) d_off[N_NODES] = N_EDGES;
}

// ---------------- CSR fill: (src, coef) per destination ----------------
__global__ void csr_fill_kernel(const void* __restrict__ ei,
                                const float* __restrict__ ew) {
    int e = blockIdx.x * blockDim.x + threadIdx.x;
    if (e >= N_EDGES) return;
    int is64 = d_idx64;
    int r = load_idx(ei, e, is64);
    int c = load_idx(ei, N_EDGES + e, is64);
    int p = atomicAdd(&d_wp[c], 1);
    d_src[p]  = r;
    d_coef[p] = ew[e] * d_dinv[r] * d_dinv[c];
}

// ---------------- GEMM (tf32 tensor cores): d_bufB16 = bf16(A @ W) ----------
#define AS_STRIDE 36
#define WS_STRIDE 132
__global__ void __launch_bounds__(256, 2) gemm_kernel(const float* __restrict__ Xext,
                                                      const float* __restrict__ W,
                                                      int use_ext) {
    __shared__ float As[128 * AS_STRIDE];   // 18KB, tf32 bits
    __shared__ float Ws[32 * WS_STRIDE];    // 16.9KB, tf32 bits
    const float* A = use_ext ? Xext : (const float*)d_bufA;

    int tid  = threadIdx.x;
    int warp = tid >> 5, lane = tid & 31;
    int wm = warp >> 1, wn = warp & 1;
    int m0 = blockIdx.x * 128;
    int grp = lane >> 2, tig = lane & 3;   // groupID, threadID-in-group

    float4 acc[2][8];
    #pragma unroll
    for (int t = 0; t < 2; t++)
        #pragma unroll
        for (int n = 0; n < 8; n++)
            acc[t][n] = make_float4(0.f, 0.f, 0.f, 0.f);

    #pragma unroll
    for (int kc = 0; kc < 4; kc++) {
        #pragma unroll
        for (int it = 0; it < 4; it++) {
            int idx = tid + it * 256;
            int k = idx >> 5, n4 = idx & 31;
            float4 w = *(const float4*)&W[(kc * 32 + k) * DIM + n4 * 4];
            unsigned* ws = (unsigned*)&Ws[k * WS_STRIDE + n4 * 4];
            uint4 t4;
            t4.x = cvt_tf32(w.x); t4.y = cvt_tf32(w.y);
            t4.z = cvt_tf32(w.z); t4.w = cvt_tf32(w.w);
            *(uint4*)ws = t4;
        }
        #pragma unroll
        for (int it = 0; it < 4; it++) {
            int idx = tid + it * 256;
            int r = idx >> 3, c4 = idx & 7;
            int gr = m0 + r;
            float4 a = make_float4(0.f, 0.f, 0.f, 0.f);
            if (gr < N_NODES)
                a = *(const float4*)&A[(size_t)gr * DIM + kc * 32 + c4 * 4];
            uint4 t4;
            t4.x = cvt_tf32(a.x); t4.y = cvt_tf32(a.y);
            t4.z = cvt_tf32(a.z); t4.w = cvt_tf32(a.w);
            *(uint4*)&As[r * AS_STRIDE + c4 * 4] = t4;
        }
        __syncthreads();

        #pragma unroll
        for (int ks = 0; ks < 4; ks++) {
            int k0 = ks * 8;
            unsigned af[2][4];
            #pragma unroll
            for (int t = 0; t < 2; t++) {
                int row = wm * 32 + t * 16 + grp;
                const unsigned* as = (const unsigned*)As;
                af[t][0] = as[(row    ) * AS_STRIDE + k0 + tig    ];
                af[t][1] = as[(row + 8) * AS_STRIDE + k0 + tig    ];
                af[t][2] = as[(row    ) * AS_STRIDE + k0 + tig + 4];
                af[t][3] = as[(row + 8) * AS_STRIDE + k0 + tig + 4];
            }
            unsigned bf[8][2];
            #pragma unroll
            for (int nt = 0; nt < 8; nt++) {
                int n = wn * 64 + nt * 8 + grp;
                const unsigned* ws = (const unsigned*)Ws;
                bf[nt][0] = ws[(k0 + tig    ) * WS_STRIDE + n];
                bf[nt][1] = ws[(k0 + tig + 4) * WS_STRIDE + n];
            }
            #pragma unroll
            for (int t = 0; t < 2; t++)
                #pragma unroll
                for (int nt = 0; nt < 8; nt++)
                    mma_tf32(acc[t][nt], af[t], bf[nt]);
        }
        __syncthreads();
    }

    // epilogue: pack adjacent-column pairs to bf16x2
    __nv_bfloat162* hb = (__nv_bfloat162*)d_bufB16;
    #pragma unroll
    for (int t = 0; t < 2; t++) {
        int row = m0 + wm * 32 + t * 16 + grp;
        #pragma unroll
        for (int nt = 0; nt < 8; nt++) {
            int col = wn * 64 + nt * 8 + 2 * tig;   // even
            if (row < N_NODES)
                hb[(size_t)row * 64 + (col >> 1)] =
                    __float22bfloat162_rn(make_float2(acc[t][nt].x, acc[t][nt].y));
            if (row + 8 < N_NODES)
                hb[(size_t)(row + 8) * 64 + (col >> 1)] =
                    __float22bfloat162_rn(make_float2(acc[t][nt].z, acc[t][nt].w));
        }
    }
}

// --- aggregation: bufA[c] = dinv2*h[c] + b + sum coef*h[src], h in bf16 -----
__global__ void __launch_bounds__(256) agg_kernel(const float* __restrict__ bias,
                                                  int do_relu) {
    int w = (blockIdx.x * blockDim.x + threadIdx.x) >> 5;
    if (w >= N_NODES) return;
    int lane = threadIdx.x & 31;
    int k = lane * 4;
    const uint2* h2 = (const uint2*)d_bufB16;   // row*32 + lane -> 4 features

    uint2 raw = __ldg(&h2[(size_t)w * 32 + lane]);
    float2 f0 = __bfloat1622float2(*(__nv_bfloat162*)&raw.x);
    float2 f1 = __bfloat1622float2(*(__nv_bfloat162*)&raw.y);
    float d2 = d_dinv2[w];
    float4 bb = *(const float4*)&bias[k];
    float4 acc;
    acc.x = d2 * f0.x + bb.x;
    acc.y = d2 * f0.y + bb.y;
    acc.z = d2 * f1.x + bb.z;
    acc.w = d2 * f1.y + bb.w;

    int e = d_off[w], end = d_off[w + 1];
    for (; e < end; e++) {
        int s   = __ldg(&d_src[e]);
        float c = __ldg(&d_coef[e]);
        uint2 r = __ldg(&h2[(size_t)s * 32 + lane]);
        float2 g0 = __bfloat1622float2(*(__nv_bfloat162*)&r.x);
        float2 g1 = __bfloat1622float2(*(__nv_bfloat162*)&r.y);
        acc.x += c * g0.x;
        acc.y += c * g0.y;
        acc.z += c * g1.x;
        acc.w += c * g1.y;
    }
    if (do_relu) {
        acc.x = fmaxf(acc.x, 0.f);
        acc.y = fmaxf(acc.y, 0.f);
        acc.z = fmaxf(acc.z, 0.f);
        acc.w = fmaxf(acc.w, 0.f);
    }
    *(float4*)&d_bufA[(size_t)w * DIM + k] = acc;
}

// ------------- fused segmented mean-pool + FC (one block per graph) ---------
__global__ void __launch_bounds__(128) pool_fc_kernel(const float* __restrict__ Wfc,
                                                      const float* __restrict__ bfc,
                                                      float* __restrict__ out) {
    __shared__ float pooled[DIM];
    int g = blockIdx.x, t = threadIdx.x;   // 128 threads
    int s0 = d_goff[g], s1 = d_goff[g + 1];
    float sum = 0.0f;
    for (int n = s0; n < s1; n++)
        sum += d_bufA[(size_t)n * DIM + t];
    float inv = 1.0f / fmaxf((float)(s1 - s0), 1.0f);
    pooled[t] = sum * inv;
    __syncthreads();
    if (t < OUT_DIM) {
        float acc = bfc[t];
        #pragma unroll
        for (int k = 0; k < DIM; k++)
            acc += pooled[k] * Wfc[k * OUT_DIM + t];
        out[g * OUT_DIM + t] = acc;
    }
}

// ---------------- launch (ONLY kernel launches — no other CUDA API) --------
extern "C" void kernel_launch(void* const* d_in, const int* in_sizes, int n_in,
                              void* d_out, int out_size) {
    const float* x     = (const float*)d_in[0];
    const void*  ei    = d_in[1];
    const float* ew    = (const float*)d_in[2];
    const void*  batch = d_in[3];
    const float* W1 = (const float*)d_in[4];
    const float* b1 = (const float*)d_in[5];
    const float* W2 = (const float*)d_in[6];
    const float* b2 = (const float*)d_in[7];
    const float* W3 = (const float*)d_in[8];
    const float* b3 = (const float*)d_in[9];
    const float* W4 = (const float*)d_in[10];
    const float* b4 = (const float*)d_in[11];
    const float* Wfc = (const float*)d_in[12];
    const float* bfc = (const float*)d_in[13];
    float* out = (float*)d_out;

    const int EB = (N_EDGES + 255) / 256;     // 1954
    const int NB = (N_NODES + 255) / 256;     // 196
    const int GEMM_GRID = (N_NODES + 127) / 128;        // 391
    const int AGG_GRID  = (N_NODES * 32 + 255) / 256;   // 6250

    init_kernel<<<NB, 256>>>(ei);
    goff_kernel<<<NB, 256>>>(batch);
    deg_kernel<<<EB, 256>>>(ei, ew);
    scan1_kernel<<<49, 1024>>>();
    scan2_kernel<<<1, 64>>>();
    scan3_kernel<<<NB, 256>>>();
    csr_fill_kernel<<<EB, 256>>>(ei, ew);

    gemm_kernel<<<GEMM_GRID, 256>>>(x, W1, 1);
    agg_kernel<<<AGG_GRID, 256>>>(b1, 1);

    gemm_kernel<<<GEMM_GRID, 256>>>(x, W2, 0);
    agg_kernel<<<AGG_GRID, 256>>>(b2, 1);

    gemm_kernel<<<GEMM_GRID, 256>>>(x, W3, 0);
    agg_kernel<<<AGG_GRID, 256>>>(b3, 1);

    gemm_kernel<<<GEMM_GRID, 256>>>(x, W4, 0);
    agg_kernel<<<AGG_GRID, 256>>>(b4, 0);

    pool_fc_kernel<<<N_GRAPHS, 128>>>(Wfc, bfc, out);
}